// round 9
// baseline (speedup 1.0000x reference)
#include <cuda_runtime.h>
#include <cstdint>

#define F 128
#define F4 (F/4)
#define MAX_ATOMS 20000
#define MAX_PAIRS 320000
#define SCAN_THREADS 1024
#define SCAN_PER ((MAX_ATOMS + SCAN_THREADS - 1) / SCAN_THREADS)   // 20

// GEMM tile config: 32 atoms (96 rows) per tile, 512 threads
#define GA 32
#define GT 512
#define VS_STRIDE 130        // u64 row stride

typedef unsigned long long u64;

// Scratch (allocation-free rule: __device__ globals)
__device__ float4 g_V[MAX_ATOMS * 3 * F4];     // V[i][c][:] accumulators
__device__ float  g_Wt[F * F];                 // Wt[f][g] = W[g][f]
__device__ int    g_cnt[MAX_ATOMS];            // pairs per atom
__device__ int    g_off[MAX_ATOMS];            // bin start offsets
__device__ int    g_pos[MAX_PAIRS];            // position of pair within its bin
__device__ int    g_recJ[MAX_PAIRS];           // binned: neighbor index j
__device__ float4 g_recU[MAX_PAIRS];           // binned: (ux*c, uy*c, uz*c, c)

__device__ __forceinline__ u64 pack64(float a, float b) {
    u64 r; asm("mov.b64 %0, {%1, %2};" : "=l"(r) : "f"(a), "f"(b)); return r;
}
__device__ __forceinline__ float2 unpack64(u64 v) {
    float2 r; asm("mov.b64 {%0, %1}, %2;" : "=f"(r.x), "=f"(r.y) : "l"(v)); return r;
}
__device__ __forceinline__ u64 mul2(u64 a, u64 b) {
    u64 r; asm("mul.rn.f32x2 %0, %1, %2;" : "=l"(r) : "l"(a), "l"(b)); return r;
}
__device__ __forceinline__ u64 add2(u64 a, u64 b) {
    u64 r; asm("add.rn.f32x2 %0, %1, %2;" : "=l"(r) : "l"(a), "l"(b)); return r;
}
#define FMA2(acc, a, b) asm("fma.rn.f32x2 %0, %1, %2, %0;" : "+l"(acc) : "l"(a), "l"(b))

// ---------------------------------------------------------------------------
// K1: zero counters + transpose W once (Wt[f][g] = W[g][f])
// ---------------------------------------------------------------------------
__global__ void init_kernel(const float* __restrict__ Wm, int n_atoms) {
    int idx = blockIdx.x * blockDim.x + threadIdx.x;
    if (idx < F * F) {
        int f = idx >> 7, g = idx & (F - 1);
        g_Wt[idx] = Wm[g * F + f];
    }
    if (idx < n_atoms) g_cnt[idx] = 0;
}

// ---------------------------------------------------------------------------
// K2: histogram of idx_i + record within-bin position
// ---------------------------------------------------------------------------
__global__ void hist_kernel(const int* __restrict__ pl, int n_pairs) {
    int p = blockIdx.x * blockDim.x + threadIdx.x;
    if (p < n_pairs) g_pos[p] = atomicAdd(&g_cnt[pl[p]], 1);
}

// ---------------------------------------------------------------------------
// K3: exclusive scan over g_cnt -> g_off (single block)
// ---------------------------------------------------------------------------
__global__ void scan_kernel(int n_atoms) {
    __shared__ int ssum[SCAN_THREADS];
    int t = threadIdx.x;
    int base = t * SCAN_PER;
    int local[SCAN_PER];
    int s = 0;
#pragma unroll
    for (int k = 0; k < SCAN_PER; k++) {
        int idx = base + k;
        int v = (idx < n_atoms) ? g_cnt[idx] : 0;
        local[k] = s;
        s += v;
    }
    ssum[t] = s;
    __syncthreads();
    for (int d = 1; d < SCAN_THREADS; d <<= 1) {
        int x = (t >= d) ? ssum[t - d] : 0;
        __syncthreads();
        ssum[t] += x;
        __syncthreads();
    }
    int excl = (t > 0) ? ssum[t - 1] : 0;
#pragma unroll
    for (int k = 0; k < SCAN_PER; k++) {
        int idx = base + k;
        if (idx < n_atoms) g_off[idx] = excl + local[k];
    }
}

// ---------------------------------------------------------------------------
// K4: scatter pairs into bins — NO atomics (position precomputed in hist);
// records store PRE-SCALED (u*c, c)
// ---------------------------------------------------------------------------
__global__ void scatter_kernel(const int* __restrict__ pl,
                               const float* __restrict__ cut,
                               const float* __restrict__ rij,
                               int n_pairs) {
    int p = blockIdx.x * blockDim.x + threadIdx.x;
    if (p >= n_pairs) return;
    int   i = pl[p];
    int   j = pl[n_pairs + p];
    float c = cut[p];
    float r0 = rij[3 * p + 0];
    float r1 = rij[3 * p + 1];
    float r2 = rij[3 * p + 2];
    float s = rsqrtf(r0 * r0 + r1 * r1 + r2 * r2) * c;
    int pos = g_off[i] + g_pos[p];
    g_recJ[pos] = j;
    g_recU[pos] = make_float4(r0 * s, r1 * s, r2 * s, c);
}

// ---------------------------------------------------------------------------
// K5: gather. One warp per atom. Records staged in smem (LDS broadcast);
// accumulation in packed f32x2; 4-wide unrolled A prefetch.
// ---------------------------------------------------------------------------
struct Acc2 { u64 r0, r1, x0, x1, y0, y1, z0, z1; };

__device__ __forceinline__ void acc2(const float4& u, const ulonglong2& a, Acc2& s) {
    u64 cc = pack64(u.w, u.w);
    u64 xx = pack64(u.x, u.x);
    u64 yy = pack64(u.y, u.y);
    u64 zz = pack64(u.z, u.z);
    u64 w0 = mul2(cc, a.x);
    u64 w1 = mul2(cc, a.y);
    s.r0 = add2(s.r0, w0);  s.r1 = add2(s.r1, w1);
    FMA2(s.x0, xx, a.x);    // NOTE: x-channel uses pre-scaled u.x (= ux*c)
    FMA2(s.x1, xx, a.y);
    FMA2(s.y0, yy, a.x);
    FMA2(s.y1, yy, a.y);
    FMA2(s.z0, zz, a.x);
    FMA2(s.z1, zz, a.y);
}

__global__ __launch_bounds__(256)
void gather_kernel(const ulonglong2* __restrict__ A2,
                   float* __restrict__ out, int n_atoms) {
    __shared__ int    sJ[8][32];
    __shared__ float4 sU[8][32];

    int warp = threadIdx.x >> 5, lane = threadIdx.x & 31;
    int w = blockIdx.x * 8 + warp;
    if (w >= n_atoms) return;
    int n = g_cnt[w];
    int base = g_off[w];

    Acc2 s = {};

    for (int c0 = 0; c0 < n; c0 += 32) {
        int m = n - c0; if (m > 32) m = 32;
        if (lane < m) {
            sJ[warp][lane] = g_recJ[base + c0 + lane];
            sU[warp][lane] = g_recU[base + c0 + lane];
        }
        __syncwarp();
        int k = 0;
        for (; k + 4 <= m; k += 4) {
            int j0 = sJ[warp][k + 0];
            int j1 = sJ[warp][k + 1];
            int j2 = sJ[warp][k + 2];
            int j3 = sJ[warp][k + 3];
            ulonglong2 a0 = __ldg(&A2[j0 * F4 + lane]);
            ulonglong2 a1 = __ldg(&A2[j1 * F4 + lane]);
            ulonglong2 a2 = __ldg(&A2[j2 * F4 + lane]);
            ulonglong2 a3 = __ldg(&A2[j3 * F4 + lane]);
            float4 u0 = sU[warp][k + 0];
            float4 u1 = sU[warp][k + 1];
            float4 u2 = sU[warp][k + 2];
            float4 u3 = sU[warp][k + 3];
            acc2(u0, a0, s); acc2(u1, a1, s); acc2(u2, a2, s); acc2(u3, a3, s);
        }
        for (; k < m; k++) {
            int j0 = sJ[warp][k];
            ulonglong2 a0 = __ldg(&A2[j0 * F4 + lane]);
            float4 u0 = sU[warp][k];
            acc2(u0, a0, s);
        }
        __syncwarp();
    }

    float2 p0, p1;
    // radial half of output
    p0 = unpack64(s.r0); p1 = unpack64(s.r1);
    *(float4*)(out + w * (2 * F) + F + lane * 4) = make_float4(p0.x, p0.y, p1.x, p1.y);
    p0 = unpack64(s.x0); p1 = unpack64(s.x1);
    g_V[(w * 3 + 0) * F4 + lane] = make_float4(p0.x, p0.y, p1.x, p1.y);
    p0 = unpack64(s.y0); p1 = unpack64(s.y1);
    g_V[(w * 3 + 1) * F4 + lane] = make_float4(p0.x, p0.y, p1.x, p1.y);
    p0 = unpack64(s.z0); p1 = unpack64(s.z1);
    g_V[(w * 3 + 2) * F4 + lane] = make_float4(p0.x, p0.y, p1.x, p1.y);
}

// ---------------------------------------------------------------------------
// K6: fused GEMM + norm. 512 threads, 32 atoms/tile -> 16 warps/SM (2x R4
// occupancy at 1 block/SM). Thread = (atom = t&31, colgroup = t>>5 -> 8 cols);
// 3 channel rows per thread in f32x2 accumulators; norm+bias in-register.
// ---------------------------------------------------------------------------
__global__ __launch_bounds__(GT)
void gemm_norm_kernel(const float* __restrict__ bias,
                      float* __restrict__ out, int n_atoms) {
    extern __shared__ char smraw[];
    float* Ws = (float*)smraw;                        // [F][F] floats (64KB)
    u64*   VsU = (u64*)(smraw + F * F * 4);           // [96][VS_STRIDE] dup (v,v)

    int t = threadIdx.x;
    int ga = t & 31;            // atom in tile (0..31)
    int cg = t >> 5;            // col group (0..15) -> cols cg*8..+7
    const ulonglong2* WsU2 = (const ulonglong2*)Ws;   // row stride 32 ull2

    {
        const float4* src = (const float4*)g_Wt;
        float4* dst = (float4*)Ws;
        for (int k = t; k < F * F / 4; k += GT) dst[k] = src[k];
    }
    __syncthreads();

    int nrows3 = n_atoms * 3;
    int tiles = (n_atoms + GA - 1) / GA;
    for (int tile = blockIdx.x; tile < tiles; tile += gridDim.x) {
        int row0 = tile * GA * 3;

        // load V rows to regs first (overlaps previous tile's compute)
        float4 vst[6];
#pragma unroll
        for (int r = 0; r < 6; r++) {
            int idx = t + r * GT;            // 0..3071
            int row = idx >> 5, f4 = idx & 31;
            int grow = row0 + row;
            vst[r] = (grow < nrows3)
                       ? __ldg(&g_V[grow * F4 + f4])
                       : make_float4(0.f, 0.f, 0.f, 0.f);
        }
        __syncthreads();
#pragma unroll
        for (int r = 0; r < 6; r++) {
            int idx = t + r * GT;
            int row = idx >> 5, f4 = idx & 31;
            ulonglong2 q0, q1;
            q0.x = pack64(vst[r].x, vst[r].x);
            q0.y = pack64(vst[r].y, vst[r].y);
            q1.x = pack64(vst[r].z, vst[r].z);
            q1.y = pack64(vst[r].w, vst[r].w);
            *(ulonglong2*)&VsU[row * VS_STRIDE + f4 * 4]     = q0;
            *(ulonglong2*)&VsU[row * VS_STRIDE + f4 * 4 + 2] = q1;
        }
        __syncthreads();

        u64 acc[3][4] = {};
#pragma unroll 4
        for (int f = 0; f < F; f += 2) {
            ulonglong2 wa0 = WsU2[f * 32 + cg * 2];
            ulonglong2 wa1 = WsU2[f * 32 + cg * 2 + 1];
            ulonglong2 wb0 = WsU2[(f + 1) * 32 + cg * 2];
            ulonglong2 wb1 = WsU2[(f + 1) * 32 + cg * 2 + 1];
#pragma unroll
            for (int c = 0; c < 3; c++) {
                ulonglong2 v = *(const ulonglong2*)&VsU[(ga * 3 + c) * VS_STRIDE + f];
                FMA2(acc[c][0], v.x, wa0.x);
                FMA2(acc[c][1], v.x, wa0.y);
                FMA2(acc[c][2], v.x, wa1.x);
                FMA2(acc[c][3], v.x, wa1.y);
                FMA2(acc[c][0], v.y, wb0.x);
                FMA2(acc[c][1], v.y, wb0.y);
                FMA2(acc[c][2], v.y, wb1.x);
                FMA2(acc[c][3], v.y, wb1.y);
            }
        }

        int atom = tile * GA + ga;
        if (atom < n_atoms) {
            float cnt = (float)g_cnt[atom];
            float4 bv0 = __ldg((const float4*)&bias[cg * 8]);
            float4 bv1 = __ldg((const float4*)&bias[cg * 8 + 4]);
            float ob[8], bb[8];
            bb[0] = bv0.x * cnt; bb[1] = bv0.y * cnt; bb[2] = bv0.z * cnt; bb[3] = bv0.w * cnt;
            bb[4] = bv1.x * cnt; bb[5] = bv1.y * cnt; bb[6] = bv1.z * cnt; bb[7] = bv1.w * cnt;
#pragma unroll
            for (int q = 0; q < 4; q++) {
                float2 vx = unpack64(acc[0][q]);
                float2 vy = unpack64(acc[1][q]);
                float2 vz = unpack64(acc[2][q]);
                float x0 = vx.x + bb[2 * q], y0 = vy.x + bb[2 * q], z0 = vz.x + bb[2 * q];
                float x1 = vx.y + bb[2 * q + 1], y1 = vy.y + bb[2 * q + 1], z1 = vz.y + bb[2 * q + 1];
                ob[2 * q]     = sqrtf(x0 * x0 + y0 * y0 + z0 * z0 + 1e-12f);
                ob[2 * q + 1] = sqrtf(x1 * x1 + y1 * y1 + z1 * z1 + 1e-12f);
            }
            float* o = &out[atom * (2 * F) + cg * 8];
            *(float4*)o       = make_float4(ob[0], ob[1], ob[2], ob[3]);
            *(float4*)(o + 4) = make_float4(ob[4], ob[5], ob[6], ob[7]);
        }
    }
}

// ---------------------------------------------------------------------------
// Launch
// ---------------------------------------------------------------------------
extern "C" void kernel_launch(void* const* d_in, const int* in_sizes, int n_in,
                              void* d_out, int out_size) {
    const float* A   = (const float*)d_in[0];   // [N, F]
    const int*   pl  = (const int*)  d_in[1];   // [2, P]
    const float* cut = (const float*)d_in[2];   // [P, 1]
    const float* rij = (const float*)d_in[3];   // [P, 3]
    const float* Wm  = (const float*)d_in[4];   // [F, F]
    const float* b   = (const float*)d_in[5];   // [F]
    float* out = (float*)d_out;                 // [N, 2F]

    int n_atoms = in_sizes[0] / F;
    int n_pairs = in_sizes[2];

    int init_n = (n_atoms > F * F) ? n_atoms : F * F;
    init_kernel<<<(init_n + 255) / 256, 256>>>(Wm, n_atoms);

    hist_kernel<<<(n_pairs + 255) / 256, 256>>>(pl, n_pairs);

    scan_kernel<<<1, SCAN_THREADS>>>(n_atoms);

    scatter_kernel<<<(n_pairs + 255) / 256, 256>>>(pl, cut, rij, n_pairs);

    gather_kernel<<<(n_atoms + 7) / 8, 256>>>((const ulonglong2*)A, out, n_atoms);

    {
        int smem = F * F * 4 + 3 * GA * VS_STRIDE * 8;   // 64KB + 97.5KB
        cudaFuncSetAttribute(gemm_norm_kernel,
                             cudaFuncAttributeMaxDynamicSharedMemorySize, smem);
        gemm_norm_kernel<<<296, GT, smem>>>(b, out, n_atoms);
    }
}